// round 5
// baseline (speedup 1.0000x reference)
#include <cuda_runtime.h>
#include <cuda_bf16.h>
#include <math.h>
#include <stdint.h>

#define B_ 16
#define A_ 256
#define NN 64
#define G_ 64
#define F_ 128
#define ROWS_TOTAL (B_*A_)   // 4096

// static device scratch (allocation-free)
__device__ float g_y[ROWS_TOTAL * F_];     // in2f output
__device__ float g_agg[ROWS_TOTAL * F_];   // aggregate before f2out
// MMA-ready weight images: [n][k-word] packed bf16x2 (hi and lo splits)
__device__ __align__(1024) uint32_t g_w1h[128 * 36];
__device__ __align__(1024) uint32_t g_w1l[128 * 36];
__device__ __align__(1024) uint32_t g_w2h[128 * 68];
__device__ __align__(1024) uint32_t g_w2l[128 * 68];

__device__ __forceinline__ float sspf(float x) {
    float ax = fabsf(x);
    return fmaxf(x, 0.0f) + __logf(1.0f + __expf(-ax)) - 0.6931471805599453f;
}

// split a pair of fp32 into packed bf16x2 hi and lo words
__device__ __forceinline__ void split2(float x, float y, uint32_t& hi, uint32_t& lo) {
    __nv_bfloat16 hx = __float2bfloat16(x);
    __nv_bfloat16 hy = __float2bfloat16(y);
    float rx = x - __bfloat162float(hx);
    float ry = y - __bfloat162float(hy);
    __nv_bfloat16 lx = __float2bfloat16(rx);
    __nv_bfloat16 ly = __float2bfloat16(ry);
    hi = (uint32_t)__bfloat16_as_ushort(hx) | ((uint32_t)__bfloat16_as_ushort(hy) << 16);
    lo = (uint32_t)__bfloat16_as_ushort(lx) | ((uint32_t)__bfloat16_as_ushort(ly) << 16);
}

// ---------------- mbarrier / bulk-copy PTX ----------------
#define MB_INIT(addr, cnt) \
    asm volatile("mbarrier.init.shared.b64 [%0], %1;" :: "r"(addr), "r"((uint32_t)(cnt)) : "memory")
#define MB_INVAL(addr) \
    asm volatile("mbarrier.inval.shared.b64 [%0];" :: "r"(addr) : "memory")
#define MB_EXPECT_TX(addr, bytes) \
    asm volatile("mbarrier.arrive.expect_tx.shared.b64 _, [%0], %1;" :: "r"(addr), "r"((uint32_t)(bytes)) : "memory")
#define MB_WAIT(addr, phase) do { \
    asm volatile("{ .reg .pred P1;\n\t" \
        "WL_%=:\n\t" \
        "mbarrier.try_wait.parity.acquire.cta.shared::cta.b64 P1, [%0], %1, 0x989680;\n\t" \
        "@P1 bra.uni WD_%=;\n\t" \
        "bra.uni WL_%=;\n\t" \
        "WD_%=: }" :: "r"(addr), "r"((uint32_t)(phase)) : "memory"); \
} while (0)
#define BULK_G2S(dst, src, bytes, mbar) \
    asm volatile("cp.async.bulk.shared::cta.global.mbarrier::complete_tx::bytes [%0], [%1], %2, [%3];" \
        :: "r"(dst), "l"(src), "r"((uint32_t)(bytes)), "r"(mbar) : "memory")
#define FENCE_PROXY() asm volatile("fence.proxy.async.shared::cta;" ::: "memory")

__device__ __forceinline__ uint32_t smem_u32(const void* p) {
    uint32_t a;
    asm("{ .reg .u64 t; cvta.to.shared.u64 t, %1; cvt.u32.u64 %0, t; }"
        : "=r"(a) : "l"(p));
    return a;
}

// m16n8k16 bf16 MMA, fp32 accumulate
__device__ __forceinline__ void mma_bf16(float c[4], const uint32_t a[4], const uint32_t b[2]) {
    asm volatile("mma.sync.aligned.m16n8k16.row.col.f32.bf16.bf16.f32 "
        "{%0,%1,%2,%3}, {%4,%5,%6,%7}, {%8,%9}, {%0,%1,%2,%3};"
        : "+f"(c[0]), "+f"(c[1]), "+f"(c[2]), "+f"(c[3])
        : "r"(a[0]), "r"(a[1]), "r"(a[2]), "r"(a[3]), "r"(b[0]), "r"(b[1]));
}

#define LDSM4(r0, r1, r2, r3, addr) \
    asm volatile("ldmatrix.sync.aligned.m8n8.x4.shared.b16 {%0,%1,%2,%3}, [%4];" \
        : "=r"(r0), "=r"(r1), "=r"(r2), "=r"(r3) : "r"(addr))

// ---------------------------------------------------------------------------
// Prologue: build hi/lo bf16 weight images, layout [n][kword], word = (k=2c, 2c+1)
// ---------------------------------------------------------------------------
__global__ void weights_img_kernel(const float* __restrict__ fw1,
                                   const float* __restrict__ fw2) {
    int t = blockIdx.x * 256 + threadIdx.x;  // 12288 total
    if (t < 4096) {                 // w1
        int n = t >> 5, c = t & 31;
        float x = fw1[(2 * c) * F_ + n];
        float y = fw1[(2 * c + 1) * F_ + n];
        uint32_t hi, lo;
        split2(x, y, hi, lo);
        g_w1h[n * 36 + c] = hi;
        g_w1l[n * 36 + c] = lo;
    } else if (t < 12288) {         // w2
        int u = t - 4096;
        int n = u >> 6, c = u & 63;
        float x = fw2[(2 * c) * F_ + n];
        float y = fw2[(2 * c + 1) * F_ + n];
        uint32_t hi, lo;
        split2(x, y, hi, lo);
        g_w2h[n * 68 + c] = hi;
        g_w2l[n * 68 + c] = lo;
    }
}

// ---------------------------------------------------------------------------
// Small fp32 GEMM (in2f / f2out): dst = act(bias + src @ w)
// 256 CTAs x 16 rows, 256 threads, 2x4 outputs per thread.
// ---------------------------------------------------------------------------
__global__ __launch_bounds__(256, 4)
void small_gemm(const float* __restrict__ src, const float* __restrict__ w,
                const float* __restrict__ bias, float* __restrict__ dst, int act) {
    __shared__ float sX[16 * 128];
    const int blk = blockIdx.x;
    const int tid = threadIdx.x;
    const float4* s0 = (const float4*)(src + (size_t)blk * 16 * F_);
#pragma unroll
    for (int q = 0; q < 2; q++) ((float4*)sX)[q * 256 + tid] = s0[q * 256 + tid];
    __syncthreads();

    const int rg = tid >> 5;        // 0..7 -> rows rg*2, rg*2+1
    const int cg = tid & 31;        // cols cg*4..cg*4+3
    float acc[2][4];
#pragma unroll
    for (int i = 0; i < 2; i++)
#pragma unroll
        for (int j = 0; j < 4; j++) acc[i][j] = 0.f;

#pragma unroll 8
    for (int k = 0; k < F_; k++) {
        float4 bv = __ldg((const float4*)(w + k * F_ + cg * 4));
        float a0 = sX[(rg * 2 + 0) * F_ + k];
        float a1 = sX[(rg * 2 + 1) * F_ + k];
        acc[0][0] += a0 * bv.x; acc[0][1] += a0 * bv.y;
        acc[0][2] += a0 * bv.z; acc[0][3] += a0 * bv.w;
        acc[1][0] += a1 * bv.x; acc[1][1] += a1 * bv.y;
        acc[1][2] += a1 * bv.z; acc[1][3] += a1 * bv.w;
    }
    float bb4[4] = {0.f, 0.f, 0.f, 0.f};
    if (bias) {
        float4 b4 = *(const float4*)(bias + cg * 4);
        bb4[0] = b4.x; bb4[1] = b4.y; bb4[2] = b4.z; bb4[3] = b4.w;
    }
#pragma unroll
    for (int i = 0; i < 2; i++) {
        int row = blk * 16 + rg * 2 + i;
        float o[4];
#pragma unroll
        for (int j = 0; j < 4; j++) {
            float v = acc[i][j] + bb4[j];
            o[j] = act ? sspf(v) : v;
        }
        *(float4*)(dst + (size_t)row * F_ + cg * 4) = make_float4(o[0], o[1], o[2], o[3]);
    }
}

// ---------------------------------------------------------------------------
// Main fused kernel: 2 atoms/CTA, bf16 hi/lo 3-MMA GEMMs, ldmatrix fragments
// ---------------------------------------------------------------------------
// smem word offsets
#define AF_H   0        // [128][36]  f_ij hi (bf16x2 words)
#define AF_L   4608     // [128][36]  f_ij lo
#define W1_H   9216     // [128][36]
#define W1_L   13824    // [128][36]     (union end 18432)
#define H_H    0        // [128][68]  H hi (aliases AF/W1 after GEMM1)
#define H_L    8704     // [128][68]
#define W2_H   18432    // [128][68]
#define W2_L   27136    // [128][68]
#define CCY    35840    // float [128 cols][132] : cc[n]*y[nbh[n]][col]
#define SB1    52736    // float [128]
#define SB2    52864    // float [128]
#define SCC    52992    // float [128]
#define SAGG   53120    // float [2][128]
#define MBAR   53376    // 2 mbarriers (4 words)
#define SMEM_WORDS 53384
#define SMEM_BYTES (SMEM_WORDS * 4)

// 3-MMA split GEMM with ldmatrix fragment loads. LD = row stride (words),
// NK = number of k16 steps. Warp tile: 64 (M) x 32 (N).
template<int LD, int NK>
__device__ __forceinline__ void gemm_split_ldsm(
    const uint32_t* Ah, const uint32_t* Al,
    const uint32_t* Bh, const uint32_t* Bl,
    int wm, int wn, int lane, float acc[16][4])
{
    const int arow = wm * 64 + (lane & 7) + ((lane >> 3) & 1) * 8;
    const int acol = ((lane >> 4) & 1) * 4;
    const int brow = wn * 32 + (lane & 7) + (lane >> 4) * 8;
    const int bcol = ((lane >> 3) & 1) * 4;
    uint32_t aH = smem_u32(Ah + arow * LD + acol);
    uint32_t aL = smem_u32(Al + arow * LD + acol);
    uint32_t bH = smem_u32(Bh + brow * LD + bcol);
    uint32_t bL = smem_u32(Bl + brow * LD + bcol);
    const uint32_t tstep = 16u * LD * 4u;   // 16 rows

#pragma unroll
    for (int ks = 0; ks < NK; ks++) {
        uint32_t bh[4][2], bl[4][2];
        LDSM4(bh[0][0], bh[0][1], bh[1][0], bh[1][1], bH);
        LDSM4(bh[2][0], bh[2][1], bh[3][0], bh[3][1], bH + tstep);
        LDSM4(bl[0][0], bl[0][1], bl[1][0], bl[1][1], bL);
        LDSM4(bl[2][0], bl[2][1], bl[3][0], bl[3][1], bL + tstep);
#pragma unroll
        for (int mt = 0; mt < 4; mt++) {
            uint32_t ah[4], al[4];
            LDSM4(ah[0], ah[1], ah[2], ah[3], aH + mt * tstep);
            LDSM4(al[0], al[1], al[2], al[3], aL + mt * tstep);
#pragma unroll
            for (int nt = 0; nt < 4; nt++) {
                mma_bf16(acc[mt * 4 + nt], ah, bh[nt]);
                mma_bf16(acc[mt * 4 + nt], ah, bl[nt]);
                mma_bf16(acc[mt * 4 + nt], al, bh[nt]);
            }
        }
        aH += 32; aL += 32; bH += 32; bL += 32;   // advance 8 k-words
    }
}

__global__ __launch_bounds__(256, 1)
void cfconv_main(const float* __restrict__ r_ij,
                 const float* __restrict__ f_ij,
                 const int*   __restrict__ neighbors,
                 const float* __restrict__ pmask,
                 const float* __restrict__ fb1,
                 const float* __restrict__ fb2) {
    extern __shared__ uint32_t smw[];
    float* smf = (float*)smw;
    const int cta  = blockIdx.x;        // atoms 2*cta, 2*cta+1
    const int tid  = threadIdx.x;
    const int wid  = tid >> 5, lane = tid & 31;
    const int wm   = wid & 1, wn = wid >> 1;   // warp grid 2x4
    const uint32_t mbar = smem_u32(smw + MBAR);

    // ---- async weight image loads ----
    if (tid == 0) {
        MB_INIT(mbar + 0, 1);
        MB_INIT(mbar + 8, 1);
        FENCE_PROXY();
        MB_EXPECT_TX(mbar + 0, 2 * 18432);
        BULK_G2S(smem_u32(smw + W1_H), (const void*)g_w1h, 18432, mbar + 0);
        BULK_G2S(smem_u32(smw + W1_L), (const void*)g_w1l, 18432, mbar + 0);
        MB_EXPECT_TX(mbar + 8, 2 * 34816);
        BULK_G2S(smem_u32(smw + W2_H), (const void*)g_w2h, 34816, mbar + 8);
        BULK_G2S(smem_u32(smw + W2_L), (const void*)g_w2l, 34816, mbar + 8);
    }

    // ---- cc, biases ----
    if (tid < 128) {
        float r = r_ij[cta * 128 + tid];
        float m = pmask[cta * 128 + tid];
        float c = (r < 5.0f) ? 0.5f * (__cosf(r * 0.6283185307179586f) + 1.0f) * m : 0.0f;
        smf[SCC + tid] = c;
        smf[SB1 + tid] = fb1[tid];
        smf[SB2 + tid] = fb2[tid];
    }

    // ---- f_ij -> hi/lo bf16x2 image [row][kword], ld 36 ----
    {
        const int r = tid >> 1, half = tid & 1;
        const float4* src = (const float4*)(f_ij + (size_t)cta * 8192 + r * 64 + half * 32);
        uint32_t* dh = smw + AF_H + r * 36 + half * 16;
        uint32_t* dl = smw + AF_L + r * 36 + half * 16;
#pragma unroll
        for (int j = 0; j < 8; j++) {
            float4 v = src[j];
            uint32_t h0, l0, h1, l1;
            split2(v.x, v.y, h0, l0);
            split2(v.z, v.w, h1, l1);
            dh[2 * j] = h0; dh[2 * j + 1] = h1;
            dl[2 * j] = l0; dl[2 * j + 1] = l1;
        }
    }
    __syncthreads();   // sCC + Af visible

    // ---- ccy[col][row] = cc[row]*y[nbh[row]][col], ld 132 ----
    {
        const int n = tid & 127, half = tid >> 7;
        const int nb = neighbors[cta * 128 + n];
        const int btch = cta >> 7;
        const float ccn = smf[SCC + n];
        const float4* yr = (const float4*)(g_y + (size_t)(btch * A_ + nb) * F_ + half * 64);
        float* ccy = smf + CCY;
#pragma unroll
        for (int q = 0; q < 16; q++) {
            float4 v = yr[q];
            int c0 = half * 64 + q * 4;
            ccy[(c0 + 0) * 132 + n] = v.x * ccn;
            ccy[(c0 + 1) * 132 + n] = v.y * ccn;
            ccy[(c0 + 2) * 132 + n] = v.z * ccn;
            ccy[(c0 + 3) * 132 + n] = v.w * ccn;
        }
    }

    const int g = lane >> 2, t = lane & 3;
    float acc[16][4];

    // ---- GEMM1: H = f_ij @ W1 (+fb1 via init), K=64 ----
    MB_WAIT(mbar + 0, 0);
#pragma unroll
    for (int mt = 0; mt < 4; mt++)
#pragma unroll
        for (int nt = 0; nt < 4; nt++) {
            int j0 = wn * 32 + nt * 8 + 2 * t;
            acc[mt * 4 + nt][0] = smf[SB1 + j0];
            acc[mt * 4 + nt][1] = smf[SB1 + j0 + 1];
            acc[mt * 4 + nt][2] = smf[SB1 + j0];
            acc[mt * 4 + nt][3] = smf[SB1 + j0 + 1];
        }
    gemm_split_ldsm<36, 4>(smw + AF_H, smw + AF_L, smw + W1_H, smw + W1_L,
                           wm, wn, lane, acc);
    __syncthreads();   // all GEMM1 smem reads done (ccy writes also done)

    // ---- epilogue 1: ssp -> hi/lo H image [row][68] (overwrites AF/W1) ----
#pragma unroll
    for (int mt = 0; mt < 4; mt++) {
#pragma unroll
        for (int nt = 0; nt < 4; nt++) {
            int r  = wm * 64 + mt * 16 + g;
            int wc = wn * 16 + nt * 4 + t;
            float s0 = sspf(acc[mt * 4 + nt][0]);
            float s1 = sspf(acc[mt * 4 + nt][1]);
            float s2 = sspf(acc[mt * 4 + nt][2]);
            float s3 = sspf(acc[mt * 4 + nt][3]);
            uint32_t hi, lo;
            split2(s0, s1, hi, lo);
            smw[H_H + r * 68 + wc] = hi;
            smw[H_L + r * 68 + wc] = lo;
            split2(s2, s3, hi, lo);
            smw[H_H + (r + 8) * 68 + wc] = hi;
            smw[H_L + (r + 8) * 68 + wc] = lo;
        }
    }
    __syncthreads();   // H visible
    MB_WAIT(mbar + 8, 0);

    // ---- GEMM2: W = H @ W2 (+fb2 via init), K=128 ----
#pragma unroll
    for (int mt = 0; mt < 4; mt++)
#pragma unroll
        for (int nt = 0; nt < 4; nt++) {
            int j0 = wn * 32 + nt * 8 + 2 * t;
            acc[mt * 4 + nt][0] = smf[SB2 + j0];
            acc[mt * 4 + nt][1] = smf[SB2 + j0 + 1];
            acc[mt * 4 + nt][2] = smf[SB2 + j0];
            acc[mt * 4 + nt][3] = smf[SB2 + j0 + 1];
        }
    gemm_split_ldsm<68, 8>(smw + H_H, smw + H_L, smw + W2_H, smw + W2_L,
                           wm, wn, lane, acc);

    // ---- epilogue 2: agg[f] = sum_rows W[r][f] * ccy[f][r] ----
    {
        const float* ccy = smf + CCY;
        float part[4][2];
#pragma unroll
        for (int nt = 0; nt < 4; nt++) { part[nt][0] = 0.f; part[nt][1] = 0.f; }
#pragma unroll
        for (int mt = 0; mt < 4; mt++) {
            int r0 = wm * 64 + mt * 16 + g;
            int r1 = r0 + 8;
#pragma unroll
            for (int nt = 0; nt < 4; nt++) {
                int j0 = wn * 32 + nt * 8 + 2 * t;
                int j1 = j0 + 1;
                part[nt][0] += acc[mt * 4 + nt][0] * ccy[j0 * 132 + r0]
                             + acc[mt * 4 + nt][2] * ccy[j0 * 132 + r1];
                part[nt][1] += acc[mt * 4 + nt][1] * ccy[j1 * 132 + r0]
                             + acc[mt * 4 + nt][3] * ccy[j1 * 132 + r1];
            }
        }
#pragma unroll
        for (int nt = 0; nt < 4; nt++)
#pragma unroll
            for (int bcol = 0; bcol < 2; bcol++) {
                float v = part[nt][bcol];
                v += __shfl_xor_sync(0xffffffffu, v, 4);
                v += __shfl_xor_sync(0xffffffffu, v, 8);
                v += __shfl_xor_sync(0xffffffffu, v, 16);
                part[nt][bcol] = v;
            }
        if (g == 0) {
#pragma unroll
            for (int nt = 0; nt < 4; nt++) {
                int j0 = wn * 32 + nt * 8 + 2 * t;
                smf[SAGG + wm * 128 + j0]     = part[nt][0];
                smf[SAGG + wm * 128 + j0 + 1] = part[nt][1];
            }
        }
    }
    __syncthreads();
    {
        const int atom = tid >> 7, c = tid & 127;
        g_agg[((size_t)cta * 2 + atom) * F_ + c] = smf[SAGG + atom * 128 + c];
    }
    __syncthreads();
    if (tid == 0) { MB_INVAL(mbar + 0); MB_INVAL(mbar + 8); }
}

// ---------------------------------------------------------------------------
extern "C" void kernel_launch(void* const* d_in, const int* in_sizes, int n_in,
                              void* d_out, int out_size) {
    const float* x        = (const float*)d_in[0];
    const float* r_ij     = (const float*)d_in[1];
    const float* f_ij     = (const float*)d_in[2];
    const int*   neighbors= (const int*)  d_in[3];
    const float* pmask    = (const float*)d_in[4];
    const float* fw1      = (const float*)d_in[5];
    const float* fb1      = (const float*)d_in[6];
    const float* fw2      = (const float*)d_in[7];
    const float* fb2      = (const float*)d_in[8];
    const float* w_in2f   = (const float*)d_in[9];
    const float* w_f2out  = (const float*)d_in[10];
    const float* b_f2out  = (const float*)d_in[11];
    float* out = (float*)d_out;

    cudaFuncSetAttribute(cfconv_main,
                         cudaFuncAttributeMaxDynamicSharedMemorySize, SMEM_BYTES);

    float* yptr;   cudaGetSymbolAddress((void**)&yptr, g_y);
    float* aggptr; cudaGetSymbolAddress((void**)&aggptr, g_agg);

    weights_img_kernel<<<48, 256>>>(fw1, fw2);
    small_gemm<<<ROWS_TOTAL / 16, 256>>>(x, w_in2f, nullptr, yptr, 0);
    cfconv_main<<<ROWS_TOTAL / 2, 256, SMEM_BYTES>>>(
        r_ij, f_ij, neighbors, pmask, fb1, fb2);
    small_gemm<<<ROWS_TOTAL / 16, 256>>>(aggptr, w_f2out, b_f2out, out, 1);
}

// round 7
// speedup vs baseline: 1.0425x; 1.0425x over previous
#include <cuda_runtime.h>
#include <cuda_bf16.h>
#include <cuda_fp16.h>
#include <math.h>
#include <stdint.h>

#define B_ 16
#define A_ 256
#define NN 64
#define G_ 64
#define F_ 128
#define ROWS_TOTAL (B_*A_)   // 4096

// static device scratch (allocation-free)
__device__ float g_y[ROWS_TOTAL * F_];     // in2f output
// fragment-order weight images: word idx = ((ks*4 + wn)*32 + lane)*16 + nt*4 + sel
// sel: 0 = hi_b0, 1 = hi_b1, 2 = lo_b0, 3 = lo_b1
__device__ __align__(16) uint32_t g_w1f[4 * 4 * 32 * 16];   // 8192 words
__device__ __align__(16) uint32_t g_w2f[8 * 4 * 32 * 16];   // 16384 words

__device__ __forceinline__ float sspf(float x) {
    float ax = fabsf(x);
    return fmaxf(x, 0.0f) + __logf(1.0f + __expf(-ax)) - 0.6931471805599453f;
}

// split a pair of fp32 into packed bf16x2 hi and lo words
__device__ __forceinline__ void split2(float x, float y, uint32_t& hi, uint32_t& lo) {
    __nv_bfloat16 hx = __float2bfloat16(x);
    __nv_bfloat16 hy = __float2bfloat16(y);
    float rx = x - __bfloat162float(hx);
    float ry = y - __bfloat162float(hy);
    __nv_bfloat16 lx = __float2bfloat16(rx);
    __nv_bfloat16 ly = __float2bfloat16(ry);
    hi = (uint32_t)__bfloat16_as_ushort(hx) | ((uint32_t)__bfloat16_as_ushort(hy) << 16);
    lo = (uint32_t)__bfloat16_as_ushort(lx) | ((uint32_t)__bfloat16_as_ushort(ly) << 16);
}

__device__ __forceinline__ uint32_t smem_u32(const void* p) {
    uint32_t a;
    asm("{ .reg .u64 t; cvta.to.shared.u64 t, %1; cvt.u32.u64 %0, t; }"
        : "=r"(a) : "l"(p));
    return a;
}

// m16n8k16 bf16 MMA, fp32 accumulate
__device__ __forceinline__ void mma_bf16(float c[4], const uint32_t a[4], const uint32_t b[2]) {
    asm volatile("mma.sync.aligned.m16n8k16.row.col.f32.bf16.bf16.f32 "
        "{%0,%1,%2,%3}, {%4,%5,%6,%7}, {%8,%9}, {%0,%1,%2,%3};"
        : "+f"(c[0]), "+f"(c[1]), "+f"(c[2]), "+f"(c[3])
        : "r"(a[0]), "r"(a[1]), "r"(a[2]), "r"(a[3]), "r"(b[0]), "r"(b[1]));
}

#define LDSM4(r0, r1, r2, r3, addr) \
    asm volatile("ldmatrix.sync.aligned.m8n8.x4.shared.b16 {%0,%1,%2,%3}, [%4];" \
        : "=r"(r0), "=r"(r1), "=r"(r2), "=r"(r3) : "r"(addr))

// ---------------------------------------------------------------------------
// Combined prologue kernel:
//   blocks [0,96): build fragment-order hi/lo weight images
//   blocks [96,96+1024): in2f  y = x @ w_in2f  (4 rows per block, 2-way k-split)
// ---------------------------------------------------------------------------
__global__ void prep_kernel(const float* __restrict__ fw1,
                            const float* __restrict__ fw2,
                            const float* __restrict__ x,
                            const float* __restrict__ w_in2f) {
    __shared__ float sX[512 + 512];
    const int bid = blockIdx.x;
    const int tid = threadIdx.x;
    if (bid < 96) {
        int t = bid * 256 + tid;       // 0..24575
        const float* fw;
        uint32_t* dst;
        int u;
        if (t < 8192) { fw = fw1; dst = g_w1f; u = t; }
        else          { fw = fw2; dst = g_w2f; u = t - 8192; }
        int j    = u & 15;
        int lane = (u >> 4) & 31;
        int wn   = (u >> 9) & 3;
        int ks   = u >> 11;
        int n  = wn * 32 + (j >> 2) * 8 + (lane >> 2);
        int kw = ks * 8 + (lane & 3) + ((j & 1) ? 4 : 0);
        float xv = fw[(2 * kw) * F_ + n];
        float yv = fw[(2 * kw + 1) * F_ + n];
        uint32_t hi, lo;
        split2(xv, yv, hi, lo);
        dst[u] = (j & 2) ? lo : hi;
    } else {
        const int blk = bid - 96;       // 0..1023, rows blk*4..blk*4+3
        float* sXd = sX;
        float* sP  = sX + 512;
        if (tid < 128)
            ((float4*)sXd)[tid] = ((const float4*)(x + (size_t)blk * 512))[tid];
        __syncthreads();
        const int kg = tid >> 7, col = tid & 127;
        float a[4] = {0.f, 0.f, 0.f, 0.f};
        const float* wp = w_in2f + (size_t)kg * 64 * F_ + col;
        const float* xb = sXd + kg * 64;
#pragma unroll 8
        for (int k = 0; k < 64; k++) {
            float wv = wp[(size_t)k * F_];
#pragma unroll
            for (int r = 0; r < 4; r++) a[r] += xb[r * 128 + k] * wv;
        }
        if (kg == 1) {
#pragma unroll
            for (int r = 0; r < 4; r++) sP[r * 128 + col] = a[r];
        }
        __syncthreads();
        if (kg == 0) {
#pragma unroll
            for (int r = 0; r < 4; r++)
                g_y[(size_t)(blk * 4 + r) * F_ + col] = a[r] + sP[r * 128 + col];
        }
    }
}

// ---------------------------------------------------------------------------
// Main fused kernel: 2 atoms/CTA, bf16 hi/lo 3-MMA GEMMs.
// A via ldmatrix from smem; B via fragment-order LDG.128 from L2 (double-buffered).
// f2out fused into the tail.
// ---------------------------------------------------------------------------
// smem word offsets
#define AF_H   0        // [128][36] f_ij hi
#define AF_L   4608     // [128][36] f_ij lo
#define H_H    0        // [128][68] H hi (aliases AF after GEMM1)
#define H_L    8704     // [128][68] H lo
#define CCYH   17408    // half [128 cols][132 rows] = 8448 words
#define SB1    25856    // float [128]
#define SB2    25984    // float [128]
#define SCC    26112    // float [128]
#define SAGG   26240    // float [2][128]
#define SMEM_WORDS 26496
#define SMEM_BYTES (SMEM_WORDS * 4)   // 105984 B -> 2 CTAs/SM

// 3-MMA split GEMM, warp tile 64(M) x 32(N). A in smem (row stride LD words),
// B from fragment-order global image (NK k16-steps).
template<int LD, int NK>
__device__ __forceinline__ void gemm_frag(
    const uint32_t* Ah, const uint32_t* Al, const uint32_t* __restrict__ Bimg,
    int wm, int wn, int lane, float acc[16][4])
{
    const int arow = wm * 64 + (lane & 7) + ((lane >> 3) & 1) * 8;
    const int acol = ((lane >> 4) & 1) * 4;
    uint32_t aH = smem_u32(Ah + arow * LD + acol);
    uint32_t aL = smem_u32(Al + arow * LD + acol);
    const uint32_t tstep = 16u * LD * 4u;

    const uint4* bp = (const uint4*)(Bimg) + ((size_t)wn * 32 + lane) * 4;
    uint4 bcur[4], bnxt[4];
#pragma unroll
    for (int j = 0; j < 4; j++) bcur[j] = bp[j];

#pragma unroll
    for (int ks = 0; ks < NK; ks++) {
        if (ks + 1 < NK) {
            const uint4* np = bp + (size_t)(ks + 1) * 512;
#pragma unroll
            for (int j = 0; j < 4; j++) bnxt[j] = np[j];
        }
#pragma unroll
        for (int mt = 0; mt < 4; mt++) {
            uint32_t ah[4], al[4];
            LDSM4(ah[0], ah[1], ah[2], ah[3], aH + mt * tstep);
            LDSM4(al[0], al[1], al[2], al[3], aL + mt * tstep);
#pragma unroll
            for (int nt = 0; nt < 4; nt++) {
                uint32_t bh[2] = {bcur[nt].x, bcur[nt].y};
                uint32_t bl[2] = {bcur[nt].z, bcur[nt].w};
                mma_bf16(acc[mt * 4 + nt], ah, bh);
                mma_bf16(acc[mt * 4 + nt], ah, bl);
                mma_bf16(acc[mt * 4 + nt], al, bh);
            }
        }
#pragma unroll
        for (int j = 0; j < 4; j++) bcur[j] = bnxt[j];
        aH += 32; aL += 32;     // advance 8 k-words (32 bytes)
    }
}

__global__ __launch_bounds__(256, 2)
void cfconv_main(const float* __restrict__ r_ij,
                 const float* __restrict__ f_ij,
                 const int*   __restrict__ neighbors,
                 const float* __restrict__ pmask,
                 const float* __restrict__ fb1,
                 const float* __restrict__ fb2,
                 const float* __restrict__ w_f2out,
                 const float* __restrict__ b_f2out,
                 float* __restrict__ out) {
    extern __shared__ uint32_t smw[];
    float* smf = (float*)smw;
    __half* ccyh = (__half*)(smw + CCYH);
    const int cta  = blockIdx.x;        // atoms 2*cta, 2*cta+1
    const int tid  = threadIdx.x;
    const int lane = tid & 31;
    const int wid  = tid >> 5;
    const int wm   = wid & 1, wn = wid >> 1;   // warp grid 2x4

    // ---- cc, biases ----
    if (tid < 128) {
        float r = r_ij[cta * 128 + tid];
        float m = pmask[cta * 128 + tid];
        float c = (r < 5.0f) ? 0.5f * (__cosf(r * 0.6283185307179586f) + 1.0f) * m : 0.0f;
        smf[SCC + tid] = c;
        smf[SB1 + tid] = fb1[tid];
        smf[SB2 + tid] = fb2[tid];
    }

    // ---- f_ij -> hi/lo bf16x2 image [row][kword], ld 36 ----
    {
        const int r = tid >> 1, half = tid & 1;
        const float4* src = (const float4*)(f_ij + (size_t)cta * 8192 + r * 64 + half * 32);
        uint32_t* dh = smw + AF_H + r * 36 + half * 16;
        uint32_t* dl = smw + AF_L + r * 36 + half * 16;
#pragma unroll
        for (int j = 0; j < 8; j++) {
            float4 v = src[j];
            uint32_t h0, l0, h1, l1;
            split2(v.x, v.y, h0, l0);
            split2(v.z, v.w, h1, l1);
            dh[2 * j] = h0; dh[2 * j + 1] = h1;
            dl[2 * j] = l0; dl[2 * j + 1] = l1;
        }
    }
    __syncthreads();   // SCC, SB1, SB2, AF visible

    // ---- gather: ccyh[col][row] = half(cc[row] * y[nbh[row]][col]) ----
    {
        const int n = tid & 127, half = tid >> 7;
        const int nb = neighbors[cta * 128 + n];
        const int btch = cta >> 7;
        const float ccn = smf[SCC + n];
        const float4* yr = (const float4*)(g_y + (size_t)(btch * A_ + nb) * F_ + half * 64);
#pragma unroll
        for (int q = 0; q < 16; q++) {
            float4 v = yr[q];
            int c0 = half * 64 + q * 4;
            ccyh[(c0 + 0) * 132 + n] = __float2half(v.x * ccn);
            ccyh[(c0 + 1) * 132 + n] = __float2half(v.y * ccn);
            ccyh[(c0 + 2) * 132 + n] = __float2half(v.z * ccn);
            ccyh[(c0 + 3) * 132 + n] = __float2half(v.w * ccn);
        }
    }

    const int g = lane >> 2, t = lane & 3;
    float acc[16][4];

    // ---- GEMM1: H = f_ij @ W1 (+fb1 via init), K=64 ----
#pragma unroll
    for (int mt = 0; mt < 4; mt++)
#pragma unroll
        for (int nt = 0; nt < 4; nt++) {
            int j0 = wn * 32 + nt * 8 + 2 * t;
            acc[mt * 4 + nt][0] = smf[SB1 + j0];
            acc[mt * 4 + nt][1] = smf[SB1 + j0 + 1];
            acc[mt * 4 + nt][2] = smf[SB1 + j0];
            acc[mt * 4 + nt][3] = smf[SB1 + j0 + 1];
        }
    gemm_frag<36, 4>(smw + AF_H, smw + AF_L, g_w1f, wm, wn, lane, acc);
    __syncthreads();   // all GEMM1 reads + gather stores done

    // ---- epilogue 1: ssp -> hi/lo H image [row][68] (overwrites AF) ----
#pragma unroll
    for (int mt = 0; mt < 4; mt++) {
#pragma unroll
        for (int nt = 0; nt < 4; nt++) {
            int r  = wm * 64 + mt * 16 + g;
            int wc = wn * 16 + nt * 4 + t;
            float s0 = sspf(acc[mt * 4 + nt][0]);
            float s1 = sspf(acc[mt * 4 + nt][1]);
            float s2 = sspf(acc[mt * 4 + nt][2]);
            float s3 = sspf(acc[mt * 4 + nt][3]);
            uint32_t hi, lo;
            split2(s0, s1, hi, lo);
            smw[H_H + r * 68 + wc] = hi;
            smw[H_L + r * 68 + wc] = lo;
            split2(s2, s3, hi, lo);
            smw[H_H + (r + 8) * 68 + wc] = hi;
            smw[H_L + (r + 8) * 68 + wc] = lo;
        }
    }
    __syncthreads();   // H visible

    // ---- GEMM2: W = H @ W2 (+fb2 via init), K=128 ----
#pragma unroll
    for (int mt = 0; mt < 4; mt++)
#pragma unroll
        for (int nt = 0; nt < 4; nt++) {
            int j0 = wn * 32 + nt * 8 + 2 * t;
            acc[mt * 4 + nt][0] = smf[SB2 + j0];
            acc[mt * 4 + nt][1] = smf[SB2 + j0 + 1];
            acc[mt * 4 + nt][2] = smf[SB2 + j0];
            acc[mt * 4 + nt][3] = smf[SB2 + j0 + 1];
        }
    gemm_frag<68, 8>(smw + H_H, smw + H_L, g_w2f, wm, wn, lane, acc);

    // ---- epilogue 2: agg[f] = sum_rows W[r][f] * ccy[f][r] ----
    {
        float part[4][2];
#pragma unroll
        for (int nt = 0; nt < 4; nt++) { part[nt][0] = 0.f; part[nt][1] = 0.f; }
#pragma unroll
        for (int mt = 0; mt < 4; mt++) {
            int r0 = wm * 64 + mt * 16 + g;
            int r1 = r0 + 8;
#pragma unroll
            for (int nt = 0; nt < 4; nt++) {
                int j0 = wn * 32 + nt * 8 + 2 * t;
                int j1 = j0 + 1;
                part[nt][0] += acc[mt * 4 + nt][0] * __half2float(ccyh[j0 * 132 + r0])
                             + acc[mt * 4 + nt][2] * __half2float(ccyh[j0 * 132 + r1]);
                part[nt][1] += acc[mt * 4 + nt][1] * __half2float(ccyh[j1 * 132 + r0])
                             + acc[mt * 4 + nt][3] * __half2float(ccyh[j1 * 132 + r1]);
            }
        }
#pragma unroll
        for (int nt = 0; nt < 4; nt++)
#pragma unroll
            for (int bcol = 0; bcol < 2; bcol++) {
                float v = part[nt][bcol];
                v += __shfl_xor_sync(0xffffffffu, v, 4);
                v += __shfl_xor_sync(0xffffffffu, v, 8);
                v += __shfl_xor_sync(0xffffffffu, v, 16);
                part[nt][bcol] = v;
            }
        if (g == 0) {
#pragma unroll
            for (int nt = 0; nt < 4; nt++) {
                int j0 = wn * 32 + nt * 8 + 2 * t;
                smf[SAGG + wm * 128 + j0]     = part[nt][0];
                smf[SAGG + wm * 128 + j0 + 1] = part[nt][1];
            }
        }
    }
    __syncthreads();

    // ---- fused f2out: out = ssp(agg @ w_f2out + b_f2out) ----
    {
        const int atom = tid >> 7, col = tid & 127;
        float v = b_f2out[col];
        const float* wp = w_f2out + col;
        const float* ap = smf + SAGG + atom * 128;
#pragma unroll 16
        for (int k = 0; k < 128; k++) {
            v += ap[k] * wp[(size_t)k * F_];
        }
        out[((size_t)cta * 2 + atom) * F_ + col] = sspf(v);
    }
}

// ---------------------------------------------------------------------------
extern "C" void kernel_launch(void* const* d_in, const int* in_sizes, int n_in,
                              void* d_out, int out_size) {
    const float* x        = (const float*)d_in[0];
    const float* r_ij     = (const float*)d_in[1];
    const float* f_ij     = (const float*)d_in[2];
    const int*   neighbors= (const int*)  d_in[3];
    const float* pmask    = (const float*)d_in[4];
    const float* fw1      = (const float*)d_in[5];
    const float* fb1      = (const float*)d_in[6];
    const float* fw2      = (const float*)d_in[7];
    const float* fb2      = (const float*)d_in[8];
    const float* w_in2f   = (const float*)d_in[9];
    const float* w_f2out  = (const float*)d_in[10];
    const float* b_f2out  = (const float*)d_in[11];
    float* out = (float*)d_out;

    cudaFuncSetAttribute(cfconv_main,
                         cudaFuncAttributeMaxDynamicSharedMemorySize, SMEM_BYTES);

    prep_kernel<<<96 + 1024, 256>>>(fw1, fw2, x, w_in2f);
    cfconv_main<<<ROWS_TOTAL / 2, 256, SMEM_BYTES>>>(
        r_ij, f_ij, neighbors, pmask, fb1, fb2, w_f2out, b_f2out, out);
}

// round 9
// speedup vs baseline: 1.3464x; 1.2915x over previous
#include <cuda_runtime.h>
#include <cuda_fp16.h>
#include <math.h>
#include <stdint.h>

#define B_ 16
#define A_ 256
#define NN 64
#define G_ 64
#define F_ 128
#define ROWS_TOTAL (B_*A_)   // 4096

// static device scratch (allocation-free)
__device__ float g_y[ROWS_TOTAL * F_];     // in2f output
// fragment-order fp16 weight images: word idx = ((ks*4 + wn)*32 + lane)*16 + nt*4 + sel
// sel: 0 = hi_b0, 1 = hi_b1, 2 = lo_b0, 3 = lo_b1
__device__ __align__(16) uint32_t g_w1f[4 * 4 * 32 * 16];   // 8192 words
__device__ __align__(16) uint32_t g_w2f[8 * 4 * 32 * 16];   // 16384 words

__device__ __forceinline__ float sspf(float x) {
    float ax = fabsf(x);
    return fmaxf(x, 0.0f) + __logf(1.0f + __expf(-ax)) - 0.6931471805599453f;
}

// split a pair of fp32 into packed fp16x2 hi and lo words (w = hi + lo, ~22 bits)
__device__ __forceinline__ void split2h(float x, float y, uint32_t& hi, uint32_t& lo) {
    __half hx = __float2half_rn(x);
    __half hy = __float2half_rn(y);
    float rx = x - __half2float(hx);
    float ry = y - __half2float(hy);
    __half lx = __float2half_rn(rx);
    __half ly = __float2half_rn(ry);
    hi = (uint32_t)__half_as_ushort(hx) | ((uint32_t)__half_as_ushort(hy) << 16);
    lo = (uint32_t)__half_as_ushort(lx) | ((uint32_t)__half_as_ushort(ly) << 16);
}

__device__ __forceinline__ uint32_t pack2h(float x, float y) {
    __half2 h = __floats2half2_rn(x, y);
    return *(uint32_t*)&h;
}

__device__ __forceinline__ uint32_t smem_u32(const void* p) {
    uint32_t a;
    asm("{ .reg .u64 t; cvta.to.shared.u64 t, %1; cvt.u32.u64 %0, t; }"
        : "=r"(a) : "l"(p));
    return a;
}

// m16n8k16 fp16 MMA, fp32 accumulate
__device__ __forceinline__ void mma_f16(float c[4], const uint32_t a[4], const uint32_t b[2]) {
    asm volatile("mma.sync.aligned.m16n8k16.row.col.f32.f16.f16.f32 "
        "{%0,%1,%2,%3}, {%4,%5,%6,%7}, {%8,%9}, {%0,%1,%2,%3};"
        : "+f"(c[0]), "+f"(c[1]), "+f"(c[2]), "+f"(c[3])
        : "r"(a[0]), "r"(a[1]), "r"(a[2]), "r"(a[3]), "r"(b[0]), "r"(b[1]));
}

#define LDSM4(r0, r1, r2, r3, addr) \
    asm volatile("ldmatrix.sync.aligned.m8n8.x4.shared.b16 {%0,%1,%2,%3}, [%4];" \
        : "=r"(r0), "=r"(r1), "=r"(r2), "=r"(r3) : "r"(addr))

// ---------------------------------------------------------------------------
// Combined prologue kernel:
//   blocks [0,96): build fragment-order hi/lo fp16 weight images
//   blocks [96,96+1024): in2f  y = x @ w_in2f  (4 rows per block, 2-way k-split)
// ---------------------------------------------------------------------------
__global__ void prep_kernel(const float* __restrict__ fw1,
                            const float* __restrict__ fw2,
                            const float* __restrict__ x,
                            const float* __restrict__ w_in2f) {
    __shared__ float sX[512 + 512];
    const int bid = blockIdx.x;
    const int tid = threadIdx.x;
    if (bid < 96) {
        int t = bid * 256 + tid;       // 0..24575
        const float* fw;
        uint32_t* dst;
        int u;
        if (t < 8192) { fw = fw1; dst = g_w1f; u = t; }
        else          { fw = fw2; dst = g_w2f; u = t - 8192; }
        int j    = u & 15;
        int lane = (u >> 4) & 31;
        int wn   = (u >> 9) & 3;
        int ks   = u >> 11;
        int n  = wn * 32 + (j >> 2) * 8 + (lane >> 2);
        int kw = ks * 8 + (lane & 3) + ((j & 1) ? 4 : 0);
        float xv = fw[(2 * kw) * F_ + n];
        float yv = fw[(2 * kw + 1) * F_ + n];
        uint32_t hi, lo;
        split2h(xv, yv, hi, lo);
        dst[u] = (j & 2) ? lo : hi;
    } else {
        const int blk = bid - 96;       // 0..1023, rows blk*4..blk*4+3
        float* sXd = sX;
        float* sP  = sX + 512;
        if (tid < 128)
            ((float4*)sXd)[tid] = ((const float4*)(x + (size_t)blk * 512))[tid];
        __syncthreads();
        const int kg = tid >> 7, col = tid & 127;
        float a[4] = {0.f, 0.f, 0.f, 0.f};
        const float* wp = w_in2f + (size_t)kg * 64 * F_ + col;
        const float* xb = sXd + kg * 64;
#pragma unroll 8
        for (int k = 0; k < 64; k++) {
            float wv = wp[(size_t)k * F_];
#pragma unroll
            for (int r = 0; r < 4; r++) a[r] += xb[r * 128 + k] * wv;
        }
        if (kg == 1) {
#pragma unroll
            for (int r = 0; r < 4; r++) sP[r * 128 + col] = a[r];
        }
        __syncthreads();
        if (kg == 0) {
#pragma unroll
            for (int r = 0; r < 4; r++)
                g_y[(size_t)(blk * 4 + r) * F_ + col] = a[r] + sP[r * 128 + col];
        }
    }
}

// ---------------------------------------------------------------------------
// Main fused kernel: 2 atoms/CTA. fp16-A 2-MMA GEMMs on the tensor pipe.
// A (single fp16) via ldmatrix from smem; W (fp16 hi/lo) via fragment LDG.128.
// f2out fused into the tail.
// ---------------------------------------------------------------------------
// smem word offsets
#define AF     0        // [128][36] f_ij fp16x2 words
#define H_     0        // [128][68] H fp16x2 (aliases AF after GEMM1)
#define CCYH   8704     // half [128 cols][132 rows] = 8448 words
#define SB1    17152    // float [128]
#define SB2    17280    // float [128]
#define SCC    17408    // float [128]
#define SAGG   17536    // float [2][128]
#define SMEM_WORDS 17792
#define SMEM_BYTES (SMEM_WORDS * 4)   // 71168 B

// 2-MMA GEMM, warp tile 64(M) x 32(N). A (fp16) in smem (row stride LD words),
// W hi/lo from fragment-order global image (NK k16-steps), double-buffered.
template<int LD, int NK>
__device__ __forceinline__ void gemm_frag(
    const uint32_t* Ah, const uint32_t* __restrict__ Bimg,
    int wm, int wn, int lane, float acc[16][4])
{
    const int arow = wm * 64 + (lane & 7) + ((lane >> 3) & 1) * 8;
    const int acol = ((lane >> 4) & 1) * 4;
    uint32_t aH = smem_u32(Ah + arow * LD + acol);
    const uint32_t tstep = 16u * LD * 4u;

    const uint4* bp = (const uint4*)(Bimg) + ((size_t)wn * 32 + lane) * 4;
    uint4 bcur[4], bnxt[4];
#pragma unroll
    for (int j = 0; j < 4; j++) bcur[j] = bp[j];

#pragma unroll
    for (int ks = 0; ks < NK; ks++) {
        if (ks + 1 < NK) {
            const uint4* np = bp + (size_t)(ks + 1) * 512;
#pragma unroll
            for (int j = 0; j < 4; j++) bnxt[j] = np[j];
        }
#pragma unroll
        for (int mt = 0; mt < 4; mt++) {
            uint32_t ah[4];
            LDSM4(ah[0], ah[1], ah[2], ah[3], aH + mt * tstep);
#pragma unroll
            for (int nt = 0; nt < 4; nt++) {
                uint32_t bh[2] = {bcur[nt].x, bcur[nt].y};
                uint32_t bl[2] = {bcur[nt].z, bcur[nt].w};
                mma_f16(acc[mt * 4 + nt], ah, bh);
                mma_f16(acc[mt * 4 + nt], ah, bl);
            }
        }
#pragma unroll
        for (int j = 0; j < 4; j++) bcur[j] = bnxt[j];
        aH += 32;     // advance 8 k-words (32 bytes)
    }
}

__global__ __launch_bounds__(256, 2)
void cfconv_main(const float* __restrict__ r_ij,
                 const float* __restrict__ f_ij,
                 const int*   __restrict__ neighbors,
                 const float* __restrict__ pmask,
                 const float* __restrict__ fb1,
                 const float* __restrict__ fb2,
                 const float* __restrict__ w_f2out,
                 const float* __restrict__ b_f2out,
                 float* __restrict__ out) {
    extern __shared__ uint32_t smw[];
    float* smf = (float*)smw;
    __half* ccyh = (__half*)(smw + CCYH);
    const int cta  = blockIdx.x;        // atoms 2*cta, 2*cta+1
    const int tid  = threadIdx.x;
    const int lane = tid & 31;
    const int wid  = tid >> 5;
    const int wm   = wid & 1, wn = wid >> 1;   // warp grid 2x4

    // ---- cc, biases ----
    if (tid < 128) {
        float r = r_ij[cta * 128 + tid];
        float m = pmask[cta * 128 + tid];
        float c = (r < 5.0f) ? 0.5f * (__cosf(r * 0.6283185307179586f) + 1.0f) * m : 0.0f;
        smf[SCC + tid] = c;
        smf[SB1 + tid] = fb1[tid];
        smf[SB2 + tid] = fb2[tid];
    }

    // ---- f_ij -> fp16x2 image [row][kword], ld 36; contiguous uint4 stores ----
    {
        const int r = tid >> 1, half = tid & 1;
        const float4* src = (const float4*)(f_ij + (size_t)cta * 8192 + r * 64 + half * 32);
        uint32_t* dh = smw + AF + r * 36 + half * 16;
#pragma unroll
        for (int j4 = 0; j4 < 4; j4++) {
            float4 v0 = src[2 * j4];
            float4 v1 = src[2 * j4 + 1];
            uint4 w;
            w.x = pack2h(v0.x, v0.y);
            w.y = pack2h(v0.z, v0.w);
            w.z = pack2h(v1.x, v1.y);
            w.w = pack2h(v1.z, v1.w);
            *(uint4*)(dh + 4 * j4) = w;
        }
    }
    __syncthreads();   // SCC, SB1, SB2, AF visible

    // ---- gather: ccyh[col][row] = half(cc[row] * y[nbh[row]][col]) ----
    {
        const int n = tid & 127, half = tid >> 7;
        const int nb = neighbors[cta * 128 + n];
        const int btch = cta >> 7;
        const float ccn = smf[SCC + n];
        const float4* yr = (const float4*)(g_y + (size_t)(btch * A_ + nb) * F_ + half * 64);
#pragma unroll
        for (int q = 0; q < 16; q++) {
            float4 v = yr[q];
            int c0 = half * 64 + q * 4;
            ccyh[(c0 + 0) * 132 + n] = __float2half(v.x * ccn);
            ccyh[(c0 + 1) * 132 + n] = __float2half(v.y * ccn);
            ccyh[(c0 + 2) * 132 + n] = __float2half(v.z * ccn);
            ccyh[(c0 + 3) * 132 + n] = __float2half(v.w * ccn);
        }
    }

    const int g = lane >> 2, t = lane & 3;
    float acc[16][4];

    // ---- GEMM1: H = f_ij @ W1 (+fb1 via init), K=64 ----
#pragma unroll
    for (int mt = 0; mt < 4; mt++)
#pragma unroll
        for (int nt = 0; nt < 4; nt++) {
            int j0 = wn * 32 + nt * 8 + 2 * t;
            acc[mt * 4 + nt][0] = smf[SB1 + j0];
            acc[mt * 4 + nt][1] = smf[SB1 + j0 + 1];
            acc[mt * 4 + nt][2] = smf[SB1 + j0];
            acc[mt * 4 + nt][3] = smf[SB1 + j0 + 1];
        }
    gemm_frag<36, 4>(smw + AF, g_w1f, wm, wn, lane, acc);
    __syncthreads();   // all GEMM1 reads + gather stores done

    // ---- epilogue 1: ssp -> fp16 H image [row][68] (overwrites AF) ----
#pragma unroll
    for (int mt = 0; mt < 4; mt++) {
#pragma unroll
        for (int nt = 0; nt < 4; nt++) {
            int r  = wm * 64 + mt * 16 + g;
            int wc = wn * 16 + nt * 4 + t;
            float s0 = sspf(acc[mt * 4 + nt][0]);
            float s1 = sspf(acc[mt * 4 + nt][1]);
            float s2 = sspf(acc[mt * 4 + nt][2]);
            float s3 = sspf(acc[mt * 4 + nt][3]);
            smw[H_ + r * 68 + wc]       = pack2h(s0, s1);
            smw[H_ + (r + 8) * 68 + wc] = pack2h(s2, s3);
        }
    }
    __syncthreads();   // H visible

    // ---- GEMM2: W = H @ W2 (+fb2 via init), K=128 ----
#pragma unroll
    for (int mt = 0; mt < 4; mt++)
#pragma unroll
        for (int nt = 0; nt < 4; nt++) {
            int j0 = wn * 32 + nt * 8 + 2 * t;
            acc[mt * 4 + nt][0] = smf[SB2 + j0];
            acc[mt * 4 + nt][1] = smf[SB2 + j0 + 1];
            acc[mt * 4 + nt][2] = smf[SB2 + j0];
            acc[mt * 4 + nt][3] = smf[SB2 + j0 + 1];
        }
    gemm_frag<68, 8>(smw + H_, g_w2f, wm, wn, lane, acc);

    // ---- epilogue 2: agg[f] = sum_rows W[r][f] * ccy[f][r] ----
    {
        float part[4][2];
#pragma unroll
        for (int nt = 0; nt < 4; nt++) { part[nt][0] = 0.f; part[nt][1] = 0.f; }
#pragma unroll
        for (int mt = 0; mt < 4; mt++) {
            int r0 = wm * 64 + mt * 16 + g;
            int r1 = r0 + 8;
#pragma unroll
            for (int nt = 0; nt < 4; nt++) {
                int j0 = wn * 32 + nt * 8 + 2 * t;
                int j1 = j0 + 1;
                part[nt][0] += acc[mt * 4 + nt][0] * __half2float(ccyh[j0 * 132 + r0])
                             + acc[mt * 4 + nt][2] * __half2float(ccyh[j0 * 132 + r1]);
                part[nt][1] += acc[mt * 4 + nt][1] * __half2float(ccyh[j1 * 132 + r0])
                             + acc[mt * 4 + nt][3] * __half2float(ccyh[j1 * 132 + r1]);
            }
        }
#pragma unroll
        for (int nt = 0; nt < 4; nt++)
#pragma unroll
            for (int bcol = 0; bcol < 2; bcol++) {
                float v = part[nt][bcol];
                v += __shfl_xor_sync(0xffffffffu, v, 4);
                v += __shfl_xor_sync(0xffffffffu, v, 8);
                v += __shfl_xor_sync(0xffffffffu, v, 16);
                part[nt][bcol] = v;
            }
        if (g == 0) {
#pragma unroll
            for (int nt = 0; nt < 4; nt++) {
                int j0 = wn * 32 + nt * 8 + 2 * t;
                smf[SAGG + wm * 128 + j0]     = part[nt][0];
                smf[SAGG + wm * 128 + j0 + 1] = part[nt][1];
            }
        }
    }
    __syncthreads();

    // ---- fused f2out: out = ssp(agg @ w_f2out + b_f2out), 2 ILP chains ----
    {
        const int atom = tid >> 7, col = tid & 127;
        float v0 = b_f2out[col], v1 = 0.f;
        const float* wp = w_f2out + col;
        const float* ap = smf + SAGG + atom * 128;
#pragma unroll 16
        for (int k = 0; k < 64; k++) {
            v0 += ap[k]      * wp[(size_t)k * F_];
            v1 += ap[k + 64] * wp[(size_t)(k + 64) * F_];
        }
        out[((size_t)cta * 2 + atom) * F_ + col] = sspf(v0 + v1);
    }
}

// ---------------------------------------------------------------------------
extern "C" void kernel_launch(void* const* d_in, const int* in_sizes, int n_in,
                              void* d_out, int out_size) {
    const float* x        = (const float*)d_in[0];
    const float* r_ij     = (const float*)d_in[1];
    const float* f_ij     = (const float*)d_in[2];
    const int*   neighbors= (const int*)  d_in[3];
    const float* pmask    = (const float*)d_in[4];
    const float* fw1      = (const float*)d_in[5];
    const float* fb1      = (const float*)d_in[6];
    const float* fw2      = (const float*)d_in[7];
    const float* fb2      = (const float*)d_in[8];
    const float* w_in2f   = (const float*)d_in[9];
    const float* w_f2out  = (const float*)d_in[10];
    const float* b_f2out  = (const float*)d_in[11];
    float* out = (float*)d_out;

    cudaFuncSetAttribute(cfconv_main,
                         cudaFuncAttributeMaxDynamicSharedMemorySize, SMEM_BYTES);

    prep_kernel<<<96 + 1024, 256>>>(fw1, fw2, x, w_in2f);
    cfconv_main<<<ROWS_TOTAL / 2, 256, SMEM_BYTES>>>(
        r_ij, f_ij, neighbors, pmask, fb1, fb2, w_f2out, b_f2out, out);
}

// round 12
// speedup vs baseline: 1.3484x; 1.0015x over previous
#include <cuda_runtime.h>
#include <cuda_fp16.h>
#include <math.h>
#include <stdint.h>

#define B_ 16
#define A_ 256
#define NN 64
#define G_ 64
#define F_ 128
#define ROWS_TOTAL (B_*A_)   // 4096

// static device scratch (allocation-free)
__device__ float g_y[ROWS_TOTAL * F_];     // in2f output
// fragment-order fp16 weight images: word idx = ((ks*4 + wn)*32 + lane)*16 + nt*4 + sel
// sel: 0 = hi_b0, 1 = hi_b1, 2 = lo_b0, 3 = lo_b1
__device__ __align__(16) uint32_t g_w1f[4 * 4 * 32 * 16];   // 8192 words
__device__ __align__(16) uint32_t g_w2f[8 * 4 * 32 * 16];   // 16384 words

__device__ __forceinline__ float sspf(float x) {
    float ax = fabsf(x);
    return fmaxf(x, 0.0f) + __logf(1.0f + __expf(-ax)) - 0.6931471805599453f;
}

// split a pair of fp32 into packed fp16x2 hi and lo words (w = hi + lo, ~22 bits)
__device__ __forceinline__ void split2h(float x, float y, uint32_t& hi, uint32_t& lo) {
    __half hx = __float2half_rn(x);
    __half hy = __float2half_rn(y);
    float rx = x - __half2float(hx);
    float ry = y - __half2float(hy);
    __half lx = __float2half_rn(rx);
    __half ly = __float2half_rn(ry);
    hi = (uint32_t)__half_as_ushort(hx) | ((uint32_t)__half_as_ushort(hy) << 16);
    lo = (uint32_t)__half_as_ushort(lx) | ((uint32_t)__half_as_ushort(ly) << 16);
}

__device__ __forceinline__ uint32_t pack2h(float x, float y) {
    __half2 h = __floats2half2_rn(x, y);
    return *(uint32_t*)&h;
}

__device__ __forceinline__ uint32_t smem_u32(const void* p) {
    uint32_t a;
    asm("{ .reg .u64 t; cvta.to.shared.u64 t, %1; cvt.u32.u64 %0, t; }"
        : "=r"(a) : "l"(p));
    return a;
}

// m16n8k16 fp16 MMA, fp32 accumulate
__device__ __forceinline__ void mma_f16(float c[4], const uint32_t a[4], const uint32_t b[2]) {
    asm volatile("mma.sync.aligned.m16n8k16.row.col.f32.f16.f16.f32 "
        "{%0,%1,%2,%3}, {%4,%5,%6,%7}, {%8,%9}, {%0,%1,%2,%3};"
        : "+f"(c[0]), "+f"(c[1]), "+f"(c[2]), "+f"(c[3])
        : "r"(a[0]), "r"(a[1]), "r"(a[2]), "r"(a[3]), "r"(b[0]), "r"(b[1]));
}

#define LDSM4(r0, r1, r2, r3, addr) \
    asm volatile("ldmatrix.sync.aligned.m8n8.x4.shared.b16 {%0,%1,%2,%3}, [%4];" \
        : "=r"(r0), "=r"(r1), "=r"(r2), "=r"(r3) : "r"(addr))
#define LDSM2(r0, r1, addr) \
    asm volatile("ldmatrix.sync.aligned.m8n8.x2.shared.b16 {%0,%1}, [%2];" \
        : "=r"(r0), "=r"(r1) : "r"(addr))

// ---------------------------------------------------------------------------
// Combined prologue kernel:
//   blocks [0,96): build fragment-order hi/lo fp16 weight images
//   blocks [96,96+1024): in2f  y = x @ w_in2f  (4 rows per block, 2-way k-split)
// ---------------------------------------------------------------------------
__global__ void prep_kernel(const float* __restrict__ fw1,
                            const float* __restrict__ fw2,
                            const float* __restrict__ x,
                            const float* __restrict__ w_in2f) {
    __shared__ float sX[512 + 512];
    const int bid = blockIdx.x;
    const int tid = threadIdx.x;
    if (bid < 96) {
        int t = bid * 256 + tid;       // 0..24575
        const float* fw;
        uint32_t* dst;
        int u;
        if (t < 8192) { fw = fw1; dst = g_w1f; u = t; }
        else          { fw = fw2; dst = g_w2f; u = t - 8192; }
        int j    = u & 15;
        int lane = (u >> 4) & 31;
        int wn   = (u >> 9) & 3;
        int ks   = u >> 11;
        int n  = wn * 32 + (j >> 2) * 8 + (lane >> 2);
        int kw = ks * 8 + (lane & 3) + ((j & 1) ? 4 : 0);
        float xv = fw[(2 * kw) * F_ + n];
        float yv = fw[(2 * kw + 1) * F_ + n];
        uint32_t hi, lo;
        split2h(xv, yv, hi, lo);
        dst[u] = (j & 2) ? lo : hi;
    } else {
        const int blk = bid - 96;       // 0..1023, rows blk*4..blk*4+3
        float* sXd = sX;
        float* sP  = sX + 512;
        if (tid < 128)
            ((float4*)sXd)[tid] = ((const float4*)(x + (size_t)blk * 512))[tid];
        __syncthreads();
        const int kg = tid >> 7, col = tid & 127;
        float a[4] = {0.f, 0.f, 0.f, 0.f};
        const float* wp = w_in2f + (size_t)kg * 64 * F_ + col;
        const float* xb = sXd + kg * 64;
#pragma unroll 8
        for (int k = 0; k < 64; k++) {
            float wv = wp[(size_t)k * F_];
#pragma unroll
            for (int r = 0; r < 4; r++) a[r] += xb[r * 128 + k] * wv;
        }
        if (kg == 1) {
#pragma unroll
            for (int r = 0; r < 4; r++) sP[r * 128 + col] = a[r];
        }
        __syncthreads();
        if (kg == 0) {
#pragma unroll
            for (int r = 0; r < 4; r++)
                g_y[(size_t)(blk * 4 + r) * F_ + col] = a[r] + sP[r * 128 + col];
        }
    }
}

// ---------------------------------------------------------------------------
// Main fused kernel: 2 atoms/CTA. fp16-A 2-MMA GEMMs on the tensor pipe.
// ccy kept row-major fp16; epilogue-2 reads it via ldmatrix (fragment-native).
// ---------------------------------------------------------------------------
// smem word offsets
#define AF     0        // [128][36] f_ij fp16x2 words
#define H_     0        // [128][68] H fp16x2 (aliases AF after GEMM1)
#define CCYH   8704     // half [128 rows][136 cols] = 8704 words
#define LDH    136      // ccy row stride in halves (rows 4 banks apart)
#define SB1    17408    // float [128]
#define SB2    17536    // float [128]
#define SCC    17664    // float [128]
#define SAGG   17792    // float [2][128]
#define SMEM_WORDS 18048
#define SMEM_BYTES (SMEM_WORDS * 4)   // 72192 B

// 2-MMA GEMM, warp tile 64(M) x 32(N). A (fp16) in smem (row stride LD words),
// W hi/lo from fragment-order global image (NK k16-steps), double-buffered.
template<int LD, int NK>
__device__ __forceinline__ void gemm_frag(
    const uint32_t* Ah, const uint32_t* __restrict__ Bimg,
    int wm, int wn, int lane, float acc[16][4])
{
    const int arow = wm * 64 + (lane & 7) + ((lane >> 3) & 1) * 8;
    const int acol = ((lane >> 4) & 1) * 4;
    uint32_t aH = smem_u32(Ah + arow * LD + acol);
    const uint32_t tstep = 16u * LD * 4u;

    const uint4* bp = (const uint4*)(Bimg) + ((size_t)wn * 32 + lane) * 4;
    uint4 bcur[4], bnxt[4];
#pragma unroll
    for (int j = 0; j < 4; j++) bcur[j] = bp[j];

#pragma unroll
    for (int ks = 0; ks < NK; ks++) {
        if (ks + 1 < NK) {
            const uint4* np = bp + (size_t)(ks + 1) * 512;
#pragma unroll
            for (int j = 0; j < 4; j++) bnxt[j] = np[j];
        }
#pragma unroll
        for (int mt = 0; mt < 4; mt++) {
            uint32_t ah[4];
            LDSM4(ah[0], ah[1], ah[2], ah[3], aH + mt * tstep);
#pragma unroll
            for (int nt = 0; nt < 4; nt++) {
                uint32_t bh[2] = {bcur[nt].x, bcur[nt].y};
                uint32_t bl[2] = {bcur[nt].z, bcur[nt].w};
                mma_f16(acc[mt * 4 + nt], ah, bh);
                mma_f16(acc[mt * 4 + nt], ah, bl);
            }
        }
#pragma unroll
        for (int j = 0; j < 4; j++) bcur[j] = bnxt[j];
        aH += 32;     // advance 8 k-words (32 bytes)
    }
}

__global__ __launch_bounds__(256, 2)
void cfconv_main(const float* __restrict__ r_ij,
                 const float* __restrict__ f_ij,
                 const int*   __restrict__ neighbors,
                 const float* __restrict__ pmask,
                 const float* __restrict__ fb1,
                 const float* __restrict__ fb2,
                 const float* __restrict__ w_f2out,
                 const float* __restrict__ b_f2out,
                 float* __restrict__ out) {
    extern __shared__ uint32_t smw[];
    float* smf = (float*)smw;
    __half* ccyh = (__half*)(smw + CCYH);
    const int cta  = blockIdx.x;        // atoms 2*cta, 2*cta+1
    const int tid  = threadIdx.x;
    const int lane = tid & 31;
    const int wid  = tid >> 5;
    const int wm   = wid & 1, wn = wid >> 1;   // warp grid 2x4

    // ---- cc, biases ----
    if (tid < 128) {
        float r = r_ij[cta * 128 + tid];
        float m = pmask[cta * 128 + tid];
        float c = (r < 5.0f) ? 0.5f * (__cosf(r * 0.6283185307179586f) + 1.0f) * m : 0.0f;
        smf[SCC + tid] = c;
        smf[SB1 + tid] = fb1[tid];
        smf[SB2 + tid] = fb2[tid];
    }

    // ---- f_ij -> fp16x2 image [row][kword], ld 36; contiguous uint4 stores ----
    {
        const int r = tid >> 1, half = tid & 1;
        const float4* src = (const float4*)(f_ij + (size_t)cta * 8192 + r * 64 + half * 32);
        uint32_t* dh = smw + AF + r * 36 + half * 16;
#pragma unroll
        for (int j4 = 0; j4 < 4; j4++) {
            float4 v0 = src[2 * j4];
            float4 v1 = src[2 * j4 + 1];
            uint4 w;
            w.x = pack2h(v0.x, v0.y);
            w.y = pack2h(v0.z, v0.w);
            w.z = pack2h(v1.x, v1.y);
            w.w = pack2h(v1.z, v1.w);
            *(uint4*)(dh + 4 * j4) = w;
        }
    }
    __syncthreads();   // SCC, SB1, SB2, AF visible

    // ---- gather: ccyh[n][col] = half(cc[n] * y[nbh[n]][col]), row-major ----
    {
        const int n = tid & 127, halfsel = tid >> 7;
        const int nb = neighbors[cta * 128 + n];
        const int btch = cta >> 7;
        const float ccn = smf[SCC + n];
        const float4* yr = (const float4*)(g_y + (size_t)(btch * A_ + nb) * F_ + halfsel * 64);
        uint4* dst = (uint4*)(ccyh + (size_t)n * LDH + halfsel * 64);
#pragma unroll
        for (int q = 0; q < 8; q++) {
            float4 a = yr[2 * q];
            float4 b = yr[2 * q + 1];
            uint4 w;
            w.x = pack2h(a.x * ccn, a.y * ccn);
            w.y = pack2h(a.z * ccn, a.w * ccn);
            w.z = pack2h(b.x * ccn, b.y * ccn);
            w.w = pack2h(b.z * ccn, b.w * ccn);
            dst[q] = w;
        }
    }

    const int g = lane >> 2, t = lane & 3;
    float acc[16][4];

    // ---- GEMM1: H = f_ij @ W1 (+fb1 via init), K=64 ----
#pragma unroll
    for (int mt = 0; mt < 4; mt++)
#pragma unroll
        for (int nt = 0; nt < 4; nt++) {
            int j0 = wn * 32 + nt * 8 + 2 * t;
            acc[mt * 4 + nt][0] = smf[SB1 + j0];
            acc[mt * 4 + nt][1] = smf[SB1 + j0 + 1];
            acc[mt * 4 + nt][2] = smf[SB1 + j0];
            acc[mt * 4 + nt][3] = smf[SB1 + j0 + 1];
        }
    gemm_frag<36, 4>(smw + AF, g_w1f, wm, wn, lane, acc);
    __syncthreads();   // all GEMM1 reads + gather stores done

    // ---- epilogue 1: ssp -> fp16 H image [row][68] (overwrites AF) ----
#pragma unroll
    for (int mt = 0; mt < 4; mt++) {
#pragma unroll
        for (int nt = 0; nt < 4; nt++) {
            int r  = wm * 64 + mt * 16 + g;
            int wc = wn * 16 + nt * 4 + t;
            float s0 = sspf(acc[mt * 4 + nt][0]);
            float s1 = sspf(acc[mt * 4 + nt][1]);
            float s2 = sspf(acc[mt * 4 + nt][2]);
            float s3 = sspf(acc[mt * 4 + nt][3]);
            smw[H_ + r * 68 + wc]       = pack2h(s0, s1);
            smw[H_ + (r + 8) * 68 + wc] = pack2h(s2, s3);
        }
    }
    __syncthreads();   // H visible

    // ---- GEMM2: W = H @ W2 (+fb2 via init), K=128 ----
#pragma unroll
    for (int mt = 0; mt < 4; mt++)
#pragma unroll
        for (int nt = 0; nt < 4; nt++) {
            int j0 = wn * 32 + nt * 8 + 2 * t;
            acc[mt * 4 + nt][0] = smf[SB2 + j0];
            acc[mt * 4 + nt][1] = smf[SB2 + j0 + 1];
            acc[mt * 4 + nt][2] = smf[SB2 + j0];
            acc[mt * 4 + nt][3] = smf[SB2 + j0 + 1];
        }
    gemm_frag<68, 8>(smw + H_, g_w2f, wm, wn, lane, acc);

    // ---- epilogue 2: agg[f] = sum_rows W[r][f] * ccy[r][f] via ldmatrix ----
    {
        // lanes 0-15 supply row addresses for ldmatrix.x2 (16 rows, 8 cols)
        const uint32_t ccy_base = smem_u32(ccyh) +
            ((uint32_t)(wm * 64 + (lane & 15)) * LDH + (uint32_t)wn * 32) * 2u;
        float part[4][2];
#pragma unroll
        for (int nt = 0; nt < 4; nt++) { part[nt][0] = 0.f; part[nt][1] = 0.f; }
#pragma unroll
        for (int mt = 0; mt < 4; mt++) {
#pragma unroll
            for (int nt = 0; nt < 4; nt++) {
                uint32_t p0, p1;
                LDSM2(p0, p1, ccy_base + (uint32_t)mt * (16u * LDH * 2u) + (uint32_t)nt * 16u);
                float2 f0 = __half22float2(*(__half2*)&p0);
                float2 f1 = __half22float2(*(__half2*)&p1);
                part[nt][0] += acc[mt * 4 + nt][0] * f0.x + acc[mt * 4 + nt][2] * f1.x;
                part[nt][1] += acc[mt * 4 + nt][1] * f0.y + acc[mt * 4 + nt][3] * f1.y;
            }
        }
#pragma unroll
        for (int nt = 0; nt < 4; nt++)
#pragma unroll
            for (int bcol = 0; bcol < 2; bcol++) {
                float v = part[nt][bcol];
                v += __shfl_xor_sync(0xffffffffu, v, 4);
                v += __shfl_xor_sync(0xffffffffu, v, 8);
                v += __shfl_xor_sync(0xffffffffu, v, 16);
                part[nt][bcol] = v;
            }
        if (g == 0) {
#pragma unroll
            for (int nt = 0; nt < 4; nt++) {
                int j0 = wn * 32 + nt * 8 + 2 * t;
                smf[SAGG + wm * 128 + j0]     = part[nt][0];
                smf[SAGG + wm * 128 + j0 + 1] = part[nt][1];
            }
        }
    }
    __syncthreads();

    // ---- fused f2out: out = ssp(agg @ w_f2out + b_f2out), 2 ILP chains ----
    {
        const int atom = tid >> 7, col = tid & 127;
        float v0 = b_f2out[col], v1 = 0.f;
        const float* wp = w_f2out + col;
        const float* ap = smf + SAGG + atom * 128;
#pragma unroll 16
        for (int k = 0; k < 64; k++) {
            v0 += ap[k]      * wp[(size_t)k * F_];
            v1 += ap[k + 64] * wp[(size_t)(k + 64) * F_];
        }
        out[((size_t)cta * 2 + atom) * F_ + col] = sspf(v0 + v1);
    }
}

// ---------------------------------------------------------------------------
extern "C" void kernel_launch(void* const* d_in, const int* in_sizes, int n_in,
                              void* d_out, int out_size) {
    const float* x        = (const float*)d_in[0];
    const float* r_ij     = (const float*)d_in[1];
    const float* f_ij     = (const float*)d_in[2];
    const int*   neighbors= (const int*)  d_in[3];
    const float* pmask    = (const float*)d_in[4];
    const float* fw1      = (const float*)d_in[5];
    const float* fb1      = (const float*)d_in[6];
    const float* fw2      = (const float*)d_in[7];
    const float* fb2      = (const float*)d_in[8];
    const float* w_in2f   = (const float*)d_in[9];
    const float* w_f2out  = (const float*)d_in[10];
    const float* b_f2out  = (const float*)d_in[11];
    float* out = (float*)d_out;

    cudaFuncSetAttribute(cfconv_main,
                         cudaFuncAttributeMaxDynamicSharedMemorySize, SMEM_BYTES);

    prep_kernel<<<96 + 1024, 256>>>(fw1, fw2, x, w_in2f);
    cfconv_main<<<ROWS_TOTAL / 2, 256, SMEM_BYTES>>>(
        r_ij, f_ij, neighbors, pmask, fb1, fb2, w_f2out, b_f2out, out);
}